// round 6
// baseline (speedup 1.0000x reference)
#include <cuda_runtime.h>
#include <cstdint>

// LIF neuron scan: x[B=64, S=1024, F=512] fp32 -> spikes (0/1) fp32.
// m = 0.95*m + x_t ; s = (m > 0.5) ; m = s ? 0 : m
// 32768 independent chains. HBM-bound: 128 MB in + 128 MB out.
// R5 (block-shared stages + 2 syncthreads/stage): DRAM 66.4%. The barriers
// lock-step all warps and the wait_group over-drains -> effective in-flight
// window ~1.5 stages. Fix: warp-AUTONOMOUS pipeline. Each warp owns 32 chains
// and a private 6-stage smem ring (4KB/stage); no __syncthreads at all;
// steady state = 4 stages = 128 lines in flight per warp, continuously.

#define LIF_B 64
#define LIF_S 1024
#define LIF_F 512
#define LIF_CH 32                         // time steps per stage
#define LIF_NSTAGE 6
#define LIF_THREADS 128                   // 4 warps, 256 blocks, all co-resident
#define LIF_STAGE_FLOATS (LIF_CH * 32)    // 32 steps x 32 chains = 1024 fl = 4KB
#define LIF_WARP_FLOATS (LIF_NSTAGE * LIF_STAGE_FLOATS)   // 6144 fl = 24KB
#define LIF_SMEM_BYTES (4 * LIF_WARP_FLOATS * 4)          // 96KB / block

__device__ __forceinline__ void cp_async16(uint32_t dst, const float* src) {
    asm volatile("cp.async.cg.shared.global [%0], [%1], 16;\n"
                 :: "r"(dst), "l"(src));
}
__device__ __forceinline__ void cp_commit() {
    asm volatile("cp.async.commit_group;\n" ::: "memory");
}
template <int N>
__device__ __forceinline__ void cp_wait() {
    asm volatile("cp.async.wait_group %0;\n" :: "n"(N) : "memory");
}

__global__ __launch_bounds__(LIF_THREADS)
void lif_scan_kernel(const float* __restrict__ x, float* __restrict__ out) {
    extern __shared__ float sm[];
    const int tid = threadIdx.x;
    const int w = tid >> 5;
    const int lane = tid & 31;

    // Warp owns 32 consecutive chains: 128B row per time step.
    const int g0 = blockIdx.x * LIF_THREADS + w * 32;
    const int b  = g0 >> 9;           // / 512
    const int f0 = g0 & (LIF_F - 1);  // % 512
    const float* xw = x + (size_t)b * (LIF_S * LIF_F) + f0;           // warp row base
    float* ow = out + (size_t)b * (LIF_S * LIF_F) + f0 + lane;        // thread column

    float* wsm = sm + w * LIF_WARP_FLOATS;                            // private ring
    const uint32_t wsm_b = (uint32_t)__cvta_generic_to_shared(wsm);

    // Fill mapping: lanes 0-7 cover step k*4+0's 128B row (8 x 16B), lanes 8-15
    // step k*4+1, etc. 8 cp.async16 per thread per stage.
    const int stepq = lane >> 3;          // step sub-index within group of 4
    const int posf  = (lane & 7) * 4;     // float offset within 128B row

    auto fill = [&](int st, int t0) {
        const uint32_t sb = wsm_b + (uint32_t)(st * LIF_STAGE_FLOATS) * 4u;
        #pragma unroll
        for (int k = 0; k < 8; k++) {
            const int step = k * 4 + stepq;
            cp_async16(sb + (uint32_t)(step * 32 + posf) * 4u,
                       xw + (size_t)(t0 + step) * LIF_F + posf);
        }
    };

    // Prologue: NSTAGE-1 = 5 stages in flight.
    #pragma unroll
    for (int s = 0; s < LIF_NSTAGE - 1; s++) {
        fill(s, s * LIF_CH);
        cp_commit();
    }

    float m = 0.0f;
    int fill_st = LIF_NSTAGE - 1;               // next ring slot to fill
    int cons_st = 0;                            // ring slot to consume
    int t_fill  = (LIF_NSTAGE - 1) * LIF_CH;    // next fill time base

    const int NIT = LIF_S / LIF_CH;             // 32 stages

    #pragma unroll 1
    for (int s = 0; s < NIT; s++) {
        if (t_fill < LIF_S)
            fill(fill_st, t_fill);
        cp_commit();                 // exactly one group per iter (may be empty)
        cp_wait<LIF_NSTAGE - 2>();   // stage s complete; 4 stages stay in flight

        const float* stage = wsm + cons_st * LIF_STAGE_FLOATS;

        float xv[LIF_CH];
        #pragma unroll
        for (int c = 0; c < LIF_CH; c++)
            xv[c] = stage[c * 32 + lane];       // conflict-free LDS

        float sv[LIF_CH];
        #pragma unroll
        for (int c = 0; c < LIF_CH; c++) {
            m = fmaf(0.95f, m, xv[c]);
            const bool fire = (m > 0.5f);
            sv[c] = fire ? 1.0f : 0.0f;
            m = fire ? 0.0f : m;
        }

        float* o = ow + (size_t)s * LIF_CH * LIF_F;
        #pragma unroll
        for (int c = 0; c < LIF_CH; c++)
            __stcs(o + (size_t)c * LIF_F, sv[c]);

        t_fill += LIF_CH;
        fill_st = (fill_st + 1 == LIF_NSTAGE) ? 0 : fill_st + 1;
        cons_st = (cons_st + 1 == LIF_NSTAGE) ? 0 : cons_st + 1;
    }
}

extern "C" void kernel_launch(void* const* d_in, const int* in_sizes, int n_in,
                              void* d_out, int out_size) {
    (void)in_sizes; (void)n_in; (void)out_size;
    const float* x = (const float*)d_in[0];
    float* out = (float*)d_out;

    static bool attr_set = false;  // idempotent host-side attribute, not work
    if (!attr_set) {
        cudaFuncSetAttribute(lif_scan_kernel,
                             cudaFuncAttributeMaxDynamicSharedMemorySize,
                             LIF_SMEM_BYTES);
        attr_set = true;
    }

    const int blocks = (LIF_B * LIF_F) / LIF_THREADS;  // 256
    lif_scan_kernel<<<blocks, LIF_THREADS, LIF_SMEM_BYTES>>>(x, out);
}

// round 8
// speedup vs baseline: 1.0156x; 1.0156x over previous
#include <cuda_runtime.h>
#include <cstdint>

// LIF neuron scan: x[B=64, S=1024, F=512] fp32 -> spikes (0/1) fp32.
// m = 0.95*m + x_t ; s = (m > 0.5) ; m = s ? 0 : m
// 32768 independent chains. HBM-bound: 128 MB in + 128 MB out.
// R5/R6 plateau ~63-66% DRAM: limiter is per-byte instruction/LSU issue cost
// (8 LDGSTS + 32 LDS + 32 STG + 128 FMA-class per warp-iter ~= 2300 cyc/SM-iter
// vs 1540 needed). Fix: 2 chains/thread (float2) -> LDS.64/STG.64 halve the
// memory-op count, recurrence gets 2-way ILP. Warp-private 6-stage cp.async
// ring (8KB/stage), no barriers. (R7 was a broker failure; resubmit.)

#define LIF_B 64
#define LIF_S 1024
#define LIF_F 512
#define LIF_CH 32                          // time steps per stage
#define LIF_NSTAGE 6
#define LIF_THREADS 64                     // 2 warps; grid 256
#define LIF_WCH 64                         // chains per warp (2 per thread)
#define LIF_STAGE_FLOATS (LIF_CH * LIF_WCH)              // 2048 fl = 8KB
#define LIF_WARP_FLOATS (LIF_NSTAGE * LIF_STAGE_FLOATS)  // 12288 fl = 48KB
#define LIF_SMEM_BYTES (2 * LIF_WARP_FLOATS * 4)         // 96KB / block

__device__ __forceinline__ void cp_async16(uint32_t dst, const float* src) {
    asm volatile("cp.async.cg.shared.global [%0], [%1], 16;\n"
                 :: "r"(dst), "l"(src));
}
__device__ __forceinline__ void cp_commit() {
    asm volatile("cp.async.commit_group;\n" ::: "memory");
}
template <int N>
__device__ __forceinline__ void cp_wait() {
    asm volatile("cp.async.wait_group %0;\n" :: "n"(N) : "memory");
}

__global__ __launch_bounds__(LIF_THREADS)
void lif_scan_kernel(const float* __restrict__ x, float* __restrict__ out) {
    extern __shared__ float sm[];
    const int tid = threadIdx.x;
    const int w = tid >> 5;
    const int lane = tid & 31;

    // Block = 128 chains; warp = 64 chains (256B row per time step).
    const int chain0 = blockIdx.x * 128 + w * LIF_WCH;
    const int b  = chain0 >> 9;           // / 512
    const int f0 = chain0 & (LIF_F - 1);  // % 512 (multiple of 64)
    const float* xw = x + (size_t)b * (LIF_S * LIF_F) + f0;          // warp row base
    float* ow = out + (size_t)b * (LIF_S * LIF_F) + f0 + 2 * lane;   // thread col (float2)

    float* wsm = sm + w * LIF_WARP_FLOATS;                           // private ring
    const uint32_t wsm_b = (uint32_t)__cvta_generic_to_shared(wsm);

    // Fill mapping: 16 lanes cover one 256B row (16 x 16B); 2 rows per instr.
    const int steph = lane >> 4;          // 0/1: which of the 2 rows
    const int posf  = (lane & 15) * 4;    // float offset within row

    auto fill = [&](int st, int t0) {
        const uint32_t sb = wsm_b + (uint32_t)(st * LIF_STAGE_FLOATS) * 4u;
        #pragma unroll
        for (int k = 0; k < 16; k++) {
            const int step = k * 2 + steph;
            cp_async16(sb + (uint32_t)(step * LIF_WCH + posf) * 4u,
                       xw + (size_t)(t0 + step) * LIF_F + posf);
        }
    };

    // Prologue: 5 stages in flight.
    #pragma unroll
    for (int s = 0; s < LIF_NSTAGE - 1; s++) {
        fill(s, s * LIF_CH);
        cp_commit();
    }

    float m0 = 0.0f, m1 = 0.0f;
    const int NIT = LIF_S / LIF_CH;  // 32

    #pragma unroll 1
    for (int s = 0; s < NIT; s++) {
        const int tf = (s + LIF_NSTAGE - 1) * LIF_CH;
        if (tf < LIF_S)
            fill((s + LIF_NSTAGE - 1) % LIF_NSTAGE, tf);
        cp_commit();                 // exactly one group per iter (may be empty)
        cp_wait<LIF_NSTAGE - 2>();   // stage s resident; 4 stages stay in flight

        const float* stage = wsm + (s % LIF_NSTAGE) * LIF_STAGE_FLOATS;
        float* o = ow + (size_t)s * LIF_CH * LIF_F;

        #pragma unroll
        for (int c = 0; c < LIF_CH; c++) {
            const float2 v = *(const float2*)(stage + c * LIF_WCH + 2 * lane);

            m0 = fmaf(0.95f, m0, v.x);
            m1 = fmaf(0.95f, m1, v.y);
            const bool fa = (m0 > 0.5f);
            const bool fb = (m1 > 0.5f);
            float2 r;
            r.x = fa ? 1.0f : 0.0f;
            r.y = fb ? 1.0f : 0.0f;
            m0 = fa ? 0.0f : m0;
            m1 = fb ? 0.0f : m1;

            __stcs((float2*)(o + (size_t)c * LIF_F), r);
        }
    }
}

extern "C" void kernel_launch(void* const* d_in, const int* in_sizes, int n_in,
                              void* d_out, int out_size) {
    (void)in_sizes; (void)n_in; (void)out_size;
    const float* x = (const float*)d_in[0];
    float* out = (float*)d_out;

    static bool attr_set = false;  // idempotent host-side attribute, not work
    if (!attr_set) {
        cudaFuncSetAttribute(lif_scan_kernel,
                             cudaFuncAttributeMaxDynamicSharedMemorySize,
                             LIF_SMEM_BYTES);
        attr_set = true;
    }

    const int blocks = (LIF_B * LIF_F) / 128;  // 256 blocks of 128 chains
    lif_scan_kernel<<<blocks, LIF_THREADS, LIF_SMEM_BYTES>>>(x, out);
}